// round 15
// baseline (speedup 1.0000x reference)
#include <cuda_runtime.h>
#include <cuda_fp16.h>
#include <cstdint>

#define BB 256
#define TT 2000
#define II 23
#define HH 128
#define MB 8                    // batches per stream
#define NST 2                   // independent streams per CTA
#define NCTA (BB / (MB * NST))  // 16
#define NSL 10                  // k-slices of 16 (128 h + 32 x-pad)
#define HSTRIDE 168             // padded fp16 row stride (336B; conflict-free)

__device__ __forceinline__ float tanh_ap(float x) {
    float y;
    asm("tanh.approx.f32 %0, %1;" : "=f"(y) : "f"(x));
    return y;
}
__device__ __forceinline__ float sigmoid_ap(float x) {
    return fmaf(tanh_ap(0.5f * x), 0.5f, 0.5f);
}
__device__ __forceinline__ uint32_t pack_h2(float lo, float hi) {
    uint32_t d;
    asm("cvt.rn.f16x2.f32 %0, %1, %2;" : "=r"(d) : "f"(hi), "f"(lo));
    return d;
}
__device__ __forceinline__ void ldsm_x2(uint32_t& r0, uint32_t& r1, uint32_t addr) {
    asm volatile("ldmatrix.sync.aligned.m8n8.x2.shared.b16 {%0,%1}, [%2];"
                 : "=r"(r0), "=r"(r1) : "r"(addr));
}
__device__ __forceinline__ void mma_f16(float& d0, float& d1, float& d2, float& d3,
                                        uint32_t a0, uint32_t a1, uint32_t a2, uint32_t a3,
                                        uint32_t b0, uint32_t b1,
                                        float c0, float c1, float c2, float c3) {
    asm volatile(
        "mma.sync.aligned.m16n8k16.row.col.f32.f16.f16.f32 "
        "{%0,%1,%2,%3},{%4,%5,%6,%7},{%8,%9},{%10,%11,%12,%13};"
        : "=f"(d0), "=f"(d1), "=f"(d2), "=f"(d3)
        : "r"(a0), "r"(a1), "r"(a2), "r"(a3), "r"(b0), "r"(b1),
          "f"(c0), "f"(c1), "f"(c2), "f"(c3));
}

// ============================================================
// Fused GRU, dual-stream: grid 16, block 256 (8 warps).
// Each CTA runs TWO independent 8-batch GRU streams; their
// ldsm/MMA/epilogue blocks interleave to fill stall slack.
// gates = [W_hh | W_ih] . [h ; x(t)]  (K=160, fp16, f32 accum).
// Weights/biases shared across streams. 1 barrier per step.
// ============================================================
__global__ __launch_bounds__(256, 1) void gru_fused(
    const float* __restrict__ x,     // [B, T, I]
    const float* __restrict__ Wih,   // [3H, I]
    const float* __restrict__ Whh,   // [3H, H]
    const float* __restrict__ bih,   // [3H]
    const float* __restrict__ bhh,   // [3H]
    float* __restrict__ out)         // [B, H]
{
    const int tid  = threadIdx.x;
    const int w    = tid >> 5;
    const int lane = tid & 31;
    const int g    = lane >> 2;
    const int tig  = lane & 3;
    const int bg0  = blockIdx.x * (MB * NST);

    __shared__ __align__(16) __half h_sh[NST][2][MB][HSTRIDE];

    // ---- B fragments (shared by both streams): slices 0..7 W_hh, 8..9 W_ih ----
    uint32_t Bf[2][3][NSL][2];
#pragma unroll
    for (int tr = 0; tr < 2; tr++) {
        const int cg = 2 * w + tr;
#pragma unroll
        for (int gate = 0; gate < 3; gate++) {
            const int orow = gate * HH + cg * 8 + g;
            const float* WrH = Whh + (size_t)orow * HH;
#pragma unroll
            for (int ks = 0; ks < 8; ks++) {
                int c = ks * 16 + 2 * tig;
                float2 v0 = *reinterpret_cast<const float2*>(WrH + c);
                float2 v1 = *reinterpret_cast<const float2*>(WrH + c + 8);
                Bf[tr][gate][ks][0] = pack_h2(v0.x, v0.y);
                Bf[tr][gate][ks][1] = pack_h2(v1.x, v1.y);
            }
            const float* WrI = Wih + (size_t)orow * II;
#pragma unroll
            for (int s = 0; s < 2; s++) {
                int c = s * 16 + 2 * tig;
                float e0 = (c     < II) ? WrI[c]     : 0.f;
                float e1 = (c + 1 < II) ? WrI[c + 1] : 0.f;
                float e2 = (c + 8 < II) ? WrI[c + 8] : 0.f;
                float e3 = (c + 9 < II) ? WrI[c + 9] : 0.f;
                Bf[tr][gate][8 + s][0] = pack_h2(e0, e1);
                Bf[tr][gate][8 + s][1] = pack_h2(e2, e3);
            }
        }
    }

    // ---- biases (shared): r,z folded; n kept separate ----
    float bs_r[2][2], bs_z[2][2], bh_n[2][2], bi_n[2][2];
#pragma unroll
    for (int tr = 0; tr < 2; tr++) {
        const int col = (2 * w + tr) * 8 + 2 * tig;
        bs_r[tr][0] = bih[col] + bhh[col];
        bs_r[tr][1] = bih[col + 1] + bhh[col + 1];
        bs_z[tr][0] = bih[HH + col] + bhh[HH + col];
        bs_z[tr][1] = bih[HH + col + 1] + bhh[HH + col + 1];
        bh_n[tr][0] = bhh[2 * HH + col];
        bh_n[tr][1] = bhh[2 * HH + col + 1];
        bi_n[tr][0] = bih[2 * HH + col];
        bi_n[tr][1] = bih[2 * HH + col + 1];
    }

    // zero all buffers (h=0; x region + pad = 0)
    for (int i = tid; i < NST * 2 * MB * HSTRIDE; i += 256)
        reinterpret_cast<__half*>(h_sh)[i] = __float2half(0.0f);

    // x staging: threads 0..95 -> stream 0, 96..191 -> stream 1
    const int xs  = tid / 96;             // stream (valid when tid<192)
    const int r96 = tid % 96;
    const int xb  = r96 / 12;
    const int xj  = r96 % 12;
    const bool xrole = (tid < 192);
    const float* xrow = x + (size_t)(bg0 + (xrole ? (xs * MB + xb) : 0)) * TT * II;

    __syncthreads();   // zeroing done

    // stage x[t=0] into buffer 0 of each stream (scalar loads; rows 4B-aligned)
    if (xrole) {
        float e0 = xrow[2 * xj];
        float e1 = (2 * xj + 1 < II) ? xrow[2 * xj + 1] : 0.f;
        *reinterpret_cast<uint32_t*>(&h_sh[xs][0][xb][HH + 2 * xj]) = pack_h2(e0, e1);
    }

    float hp[NST][2][2]   = {{{0.f,0.f},{0.f,0.f}},{{0.f,0.f},{0.f,0.f}}};
    float hsum[NST][2][2] = {{{0.f,0.f},{0.f,0.f}},{{0.f,0.f},{0.f,0.f}}};

    const int arow  = lane & 7;
    const int ahalf = (lane >> 3) & 1;
    const uint32_t hoff = arow * (HSTRIDE * 2) + ahalf * 16;
    uint32_t hb[NST][2];
#pragma unroll
    for (int s = 0; s < NST; s++) {
        hb[s][0] = (uint32_t)__cvta_generic_to_shared(&h_sh[s][0][0][0]) + hoff;
        hb[s][1] = (uint32_t)__cvta_generic_to_shared(&h_sh[s][1][0][0]) + hoff;
    }

    __syncthreads();

    int cur = 0;
    for (int t = 0; t < TT; t++) {
        // prefetch x[t+1] for this thread's stream (LDG issued early)
        uint32_t xw = 0u;
        const bool xdo = xrole && (t + 1 < TT);
        if (xdo) {
            const float* xr = xrow + (size_t)(t + 1) * II;
            float e0 = xr[2 * xj];
            float e1 = (2 * xj + 1 < II) ? xr[2 * xj + 1] : 0.f;
            xw = pack_h2(e0, e1);
        }

        float Dr[NST][2][2], Dz[NST][2][2], Dnh[NST][2][2], Dnx[NST][2][2];

        // ---- MMA blocks, stream-major (A-frags scoped per stream) ----
#pragma unroll
        for (int s = 0; s < NST; s++) {
            uint32_t A0[NSL], A2[NSL];
#pragma unroll
            for (int ks = 0; ks < NSL; ks++)
                ldsm_x2(A0[ks], A2[ks], hb[s][cur] + ks * 32);

#pragma unroll
            for (int tr = 0; tr < 2; tr++) {
                {
                    float d0 = 0.f, d1 = 0.f, d2 = 0.f, d3 = 0.f;
#pragma unroll
                    for (int ks = 0; ks < NSL; ks++)
                        mma_f16(d0, d1, d2, d3, A0[ks], 0u, A2[ks], 0u,
                                Bf[tr][0][ks][0], Bf[tr][0][ks][1], d0, d1, d2, d3);
                    Dr[s][tr][0] = d0; Dr[s][tr][1] = d1;
                }
                {
                    float d0 = 0.f, d1 = 0.f, d2 = 0.f, d3 = 0.f;
#pragma unroll
                    for (int ks = 0; ks < NSL; ks++)
                        mma_f16(d0, d1, d2, d3, A0[ks], 0u, A2[ks], 0u,
                                Bf[tr][1][ks][0], Bf[tr][1][ks][1], d0, d1, d2, d3);
                    Dz[s][tr][0] = d0; Dz[s][tr][1] = d1;
                }
                {
                    float d0 = 0.f, d1 = 0.f, d2 = 0.f, d3 = 0.f;
#pragma unroll
                    for (int ks = 0; ks < 8; ks++)
                        mma_f16(d0, d1, d2, d3, A0[ks], 0u, A2[ks], 0u,
                                Bf[tr][2][ks][0], Bf[tr][2][ks][1], d0, d1, d2, d3);
                    Dnh[s][tr][0] = d0; Dnh[s][tr][1] = d1;
                    float f0 = 0.f, f1 = 0.f, f2 = 0.f, f3 = 0.f;
#pragma unroll
                    for (int ks = 8; ks < NSL; ks++)
                        mma_f16(f0, f1, f2, f3, A0[ks], 0u, A2[ks], 0u,
                                Bf[tr][2][ks][0], Bf[tr][2][ks][1], f0, f1, f2, f3);
                    Dnx[s][tr][0] = f0; Dnx[s][tr][1] = f1;
                }
            }
        }

        // ---- epilogues (fp32, same numerics as R11) ----
#pragma unroll
        for (int s = 0; s < NST; s++) {
#pragma unroll
            for (int tr = 0; tr < 2; tr++) {
                float rr0 = sigmoid_ap(Dr[s][tr][0] + bs_r[tr][0]);
                float rr1 = sigmoid_ap(Dr[s][tr][1] + bs_r[tr][1]);
                float zz0 = sigmoid_ap(Dz[s][tr][0] + bs_z[tr][0]);
                float zz1 = sigmoid_ap(Dz[s][tr][1] + bs_z[tr][1]);
                float nn0 = tanh_ap(fmaf(rr0, Dnh[s][tr][0] + bh_n[tr][0],
                                         Dnx[s][tr][0] + bi_n[tr][0]));
                float nn1 = tanh_ap(fmaf(rr1, Dnh[s][tr][1] + bh_n[tr][1],
                                         Dnx[s][tr][1] + bi_n[tr][1]));

                float h0 = fmaf(zz0, hp[s][tr][0] - nn0, nn0);
                float h1 = fmaf(zz1, hp[s][tr][1] - nn1, nn1);
                hp[s][tr][0] = h0;  hp[s][tr][1] = h1;
                hsum[s][tr][0] += h0;  hsum[s][tr][1] += h1;

                const int col = (2 * w + tr) * 8 + 2 * tig;
                *reinterpret_cast<uint32_t*>(&h_sh[s][cur ^ 1][g][col]) =
                    pack_h2(h0, h1);
            }
        }

        // stage x[t+1] into the next buffer
        if (xdo)
            *reinterpret_cast<uint32_t*>(&h_sh[xs][cur ^ 1][xb][HH + 2 * xj]) = xw;

        __syncthreads();
        cur ^= 1;
    }

#pragma unroll
    for (int s = 0; s < NST; s++)
#pragma unroll
        for (int tr = 0; tr < 2; tr++) {
            const int col = (2 * w + tr) * 8 + 2 * tig;
            out[(bg0 + s * MB + g) * HH + col]     = hsum[s][tr][0] * (1.0f / (float)TT);
            out[(bg0 + s * MB + g) * HH + col + 1] = hsum[s][tr][1] * (1.0f / (float)TT);
        }
}

extern "C" void kernel_launch(void* const* d_in, const int* in_sizes, int n_in,
                              void* d_out, int out_size) {
    const float* x   = (const float*)d_in[0];
    const float* Wih = (const float*)d_in[1];
    const float* Whh = (const float*)d_in[2];
    const float* bih = (const float*)d_in[3];
    const float* bhh = (const float*)d_in[4];
    float* out = (float*)d_out;
    (void)in_sizes; (void)n_in; (void)out_size;

    gru_fused<<<NCTA, 256>>>(x, Wih, Whh, bih, bhh, out);
}

// round 16
// speedup vs baseline: 1.7109x; 1.7109x over previous
#include <cuda_runtime.h>
#include <cuda_fp16.h>
#include <cstdint>

#define BB 256
#define TT 2000
#define II 23
#define HH 128
#define MB 16                   // batches per CTA (full m16 A rows)
#define NCTA (BB / MB)          // 16
#define NSL 10                  // k-slices of 16 (128 h + 32 x-pad)
#define HSTRIDE 168             // padded fp16 row stride (336B; conflict-free)

__device__ __forceinline__ float tanh_ap(float x) {
    float y;
    asm("tanh.approx.f32 %0, %1;" : "=f"(y) : "f"(x));
    return y;
}
__device__ __forceinline__ uint32_t pack_h2(float lo, float hi) {
    uint32_t d;
    asm("cvt.rn.f16x2.f32 %0, %1, %2;" : "=r"(d) : "f"(hi), "f"(lo));
    return d;
}
__device__ __forceinline__ uint32_t tanh_h2(uint32_t v) {
    uint32_t d;
    asm("tanh.approx.f16x2 %0, %1;" : "=r"(d) : "r"(v));
    return d;
}
__device__ __forceinline__ uint32_t hfma2_(uint32_t a, uint32_t b, uint32_t c) {
    uint32_t d;
    asm("fma.rn.f16x2 %0, %1, %2, %3;" : "=r"(d) : "r"(a), "r"(b), "r"(c));
    return d;
}
__device__ __forceinline__ void ldsm_x4(uint32_t& r0, uint32_t& r1, uint32_t& r2,
                                        uint32_t& r3, uint32_t addr) {
    asm volatile("ldmatrix.sync.aligned.m8n8.x4.shared.b16 {%0,%1,%2,%3}, [%4];"
                 : "=r"(r0), "=r"(r1), "=r"(r2), "=r"(r3) : "r"(addr));
}
__device__ __forceinline__ void mma_f16(float& d0, float& d1, float& d2, float& d3,
                                        uint32_t a0, uint32_t a1, uint32_t a2, uint32_t a3,
                                        uint32_t b0, uint32_t b1,
                                        float c0, float c1, float c2, float c3) {
    asm volatile(
        "mma.sync.aligned.m16n8k16.row.col.f32.f16.f16.f32 "
        "{%0,%1,%2,%3},{%4,%5,%6,%7},{%8,%9},{%10,%11,%12,%13};"
        : "=f"(d0), "=f"(d1), "=f"(d2), "=f"(d3)
        : "r"(a0), "r"(a1), "r"(a2), "r"(a3), "r"(b0), "r"(b1),
          "f"(c0), "f"(c1), "f"(c2), "f"(c3));
}

// ============================================================
// Fused GRU, full-M: grid 16, block 256 (8 warps), 16 batches/CTA.
// Same 60 MMAs/warp/step as before, but A rows 8..15 now carry
// batches 8..15 (previously zero padding). ldmatrix.x4 A loads.
// r,z gates: tanh.approx.f16x2 (weights pre-scaled 0.5);
// n gate + h update fp32. 1 barrier/step.
// ============================================================
__global__ __launch_bounds__(256, 1) void gru_fused(
    const float* __restrict__ x,     // [B, T, I]
    const float* __restrict__ Wih,   // [3H, I]
    const float* __restrict__ Whh,   // [3H, H]
    const float* __restrict__ bih,   // [3H]
    const float* __restrict__ bhh,   // [3H]
    float* __restrict__ out)         // [B, H]
{
    const int tid  = threadIdx.x;
    const int w    = tid >> 5;
    const int lane = tid & 31;
    const int g    = lane >> 2;      // batch row (0..7; +8 for d2,d3)
    const int tig  = lane & 3;
    const int bg0  = blockIdx.x * MB;

    __shared__ __align__(16) __half h_sh[2][MB][HSTRIDE];

    // ---- B fragments: slices 0..7 W_hh, 8..9 W_ih (zero-padded) ----
    // r,z scaled by 0.5 (sigmoid via tanh); n unscaled.
    uint32_t Bf[2][3][NSL][2];
#pragma unroll
    for (int tr = 0; tr < 2; tr++) {
        const int cg = 2 * w + tr;
#pragma unroll
        for (int gate = 0; gate < 3; gate++) {
            const float sc = (gate < 2) ? 0.5f : 1.0f;
            const int orow = gate * HH + cg * 8 + g;
            const float* WrH = Whh + (size_t)orow * HH;
#pragma unroll
            for (int ks = 0; ks < 8; ks++) {
                int c = ks * 16 + 2 * tig;
                float2 v0 = *reinterpret_cast<const float2*>(WrH + c);
                float2 v1 = *reinterpret_cast<const float2*>(WrH + c + 8);
                Bf[tr][gate][ks][0] = pack_h2(v0.x * sc, v0.y * sc);
                Bf[tr][gate][ks][1] = pack_h2(v1.x * sc, v1.y * sc);
            }
            const float* WrI = Wih + (size_t)orow * II;
#pragma unroll
            for (int s = 0; s < 2; s++) {
                int c = s * 16 + 2 * tig;
                float e0 = (c     < II) ? WrI[c]     * sc : 0.f;
                float e1 = (c + 1 < II) ? WrI[c + 1] * sc : 0.f;
                float e2 = (c + 8 < II) ? WrI[c + 8] * sc : 0.f;
                float e3 = (c + 9 < II) ? WrI[c + 9] * sc : 0.f;
                Bf[tr][gate][8 + s][0] = pack_h2(e0, e1);
                Bf[tr][gate][8 + s][1] = pack_h2(e2, e3);
            }
        }
    }

    // ---- biases (per col; shared across batch rows) ----
    float bs_r[2][2], bs_z[2][2], bh_n[2][2], bi_n[2][2];
#pragma unroll
    for (int tr = 0; tr < 2; tr++) {
        const int col = (2 * w + tr) * 8 + 2 * tig;
        bs_r[tr][0] = 0.5f * (bih[col] + bhh[col]);
        bs_r[tr][1] = 0.5f * (bih[col + 1] + bhh[col + 1]);
        bs_z[tr][0] = 0.5f * (bih[HH + col] + bhh[HH + col]);
        bs_z[tr][1] = 0.5f * (bih[HH + col + 1] + bhh[HH + col + 1]);
        bh_n[tr][0] = bhh[2 * HH + col];
        bh_n[tr][1] = bhh[2 * HH + col + 1];
        bi_n[tr][0] = bih[2 * HH + col];
        bi_n[tr][1] = bih[2 * HH + col + 1];
    }

    // zero both buffers
    for (int i = tid; i < 2 * MB * HSTRIDE; i += 256)
        reinterpret_cast<__half*>(h_sh)[i] = __float2half(0.0f);

    // x staging: threads 0..191 -> (batch xb 0..15, word xj 0..11)
    const int xb = tid / 12;
    const int xj = tid % 12;
    const bool xrole = (tid < 192);
    const float* xrow = x + (size_t)(bg0 + (xrole ? xb : 0)) * TT * II;

    __syncthreads();

    // stage x[t=0] into buffer 0 (scalar loads; rows only 4B-aligned)
    if (xrole) {
        float e0 = xrow[2 * xj];
        float e1 = (2 * xj + 1 < II) ? xrow[2 * xj + 1] : 0.f;
        *reinterpret_cast<uint32_t*>(&h_sh[0][xb][HH + 2 * xj]) = pack_h2(e0, e1);
    }

    // per-thread h state: [tr][rowgroup(g / g+8)][col 0/1]
    float hp[2][2][2]   = {{{0.f,0.f},{0.f,0.f}},{{0.f,0.f},{0.f,0.f}}};
    float hsum[2][2][2] = {{{0.f,0.f},{0.f,0.f}},{{0.f,0.f},{0.f,0.f}}};

    // ldmatrix.x4 addressing: lanes 0..15 -> rows 0..15 (k-low 8),
    // lanes 16..31 -> rows 0..15 (k-high 8)
    const uint32_t hoff = (lane & 15) * (HSTRIDE * 2) + (lane >> 4) * 16;
    uint32_t hbase[2];
    hbase[0] = (uint32_t)__cvta_generic_to_shared(&h_sh[0][0][0]) + hoff;
    hbase[1] = (uint32_t)__cvta_generic_to_shared(&h_sh[1][0][0]) + hoff;

    const uint32_t H05 = 0x38003800u;   // half2(0.5, 0.5)

    __syncthreads();

    int cur = 0;
    for (int t = 0; t < TT; t++) {
        // prefetch x[t+1] (threads 0..191)
        uint32_t xw = 0u;
        const bool xdo = xrole && (t + 1 < TT);
        if (xdo) {
            const float* xr = xrow + (size_t)(t + 1) * II;
            float e0 = xr[2 * xj];
            float e1 = (2 * xj + 1 < II) ? xr[2 * xj + 1] : 0.f;
            xw = pack_h2(e0, e1);
        }

        // A fragments: 10 k-slices of [h ; x], full 16 rows
        uint32_t A0[NSL], A1[NSL], A2[NSL], A3[NSL];
#pragma unroll
        for (int ks = 0; ks < NSL; ks++)
            ldsm_x4(A0[ks], A1[ks], A2[ks], A3[ks], hbase[cur] + ks * 32);

        // ---- MMA chains (all 4 outputs live now) ----
        float Dr[2][4], Dz[2][4], Dnh[2][4], Dnx[2][4];
#pragma unroll
        for (int tr = 0; tr < 2; tr++) {
            {
                float d0 = 0.f, d1 = 0.f, d2 = 0.f, d3 = 0.f;
#pragma unroll
                for (int ks = 0; ks < NSL; ks++)
                    mma_f16(d0, d1, d2, d3, A0[ks], A1[ks], A2[ks], A3[ks],
                            Bf[tr][0][ks][0], Bf[tr][0][ks][1], d0, d1, d2, d3);
                Dr[tr][0] = d0; Dr[tr][1] = d1; Dr[tr][2] = d2; Dr[tr][3] = d3;
            }
            {
                float d0 = 0.f, d1 = 0.f, d2 = 0.f, d3 = 0.f;
#pragma unroll
                for (int ks = 0; ks < NSL; ks++)
                    mma_f16(d0, d1, d2, d3, A0[ks], A1[ks], A2[ks], A3[ks],
                            Bf[tr][1][ks][0], Bf[tr][1][ks][1], d0, d1, d2, d3);
                Dz[tr][0] = d0; Dz[tr][1] = d1; Dz[tr][2] = d2; Dz[tr][3] = d3;
            }
            {
                float d0 = 0.f, d1 = 0.f, d2 = 0.f, d3 = 0.f;
#pragma unroll
                for (int ks = 0; ks < 8; ks++)
                    mma_f16(d0, d1, d2, d3, A0[ks], A1[ks], A2[ks], A3[ks],
                            Bf[tr][2][ks][0], Bf[tr][2][ks][1], d0, d1, d2, d3);
                Dnh[tr][0] = d0; Dnh[tr][1] = d1; Dnh[tr][2] = d2; Dnh[tr][3] = d3;
                float f0 = 0.f, f1 = 0.f, f2 = 0.f, f3 = 0.f;
#pragma unroll
                for (int ks = 8; ks < NSL; ks++)
                    mma_f16(f0, f1, f2, f3, A0[ks], A1[ks], A2[ks], A3[ks],
                            Bf[tr][2][ks][0], Bf[tr][2][ks][1], f0, f1, f2, f3);
                Dnx[tr][0] = f0; Dnx[tr][1] = f1; Dnx[tr][2] = f2; Dnx[tr][3] = f3;
            }
        }

        // ---- epilogue: r,z packed tanh; n + h update fp32 ----
#pragma unroll
        for (int tr = 0; tr < 2; tr++) {
            const int col = (2 * w + tr) * 8 + 2 * tig;
#pragma unroll
            for (int rg = 0; rg < 2; rg++) {          // rows g and g+8
                const int i0 = 2 * rg, i1 = 2 * rg + 1;
                uint32_t sr2 = hfma2_(tanh_h2(pack_h2(Dr[tr][i0] + bs_r[tr][0],
                                                      Dr[tr][i1] + bs_r[tr][1])),
                                      H05, H05);
                uint32_t sz2 = hfma2_(tanh_h2(pack_h2(Dz[tr][i0] + bs_z[tr][0],
                                                      Dz[tr][i1] + bs_z[tr][1])),
                                      H05, H05);
                float2 rf = __half22float2(*reinterpret_cast<__half2*>(&sr2));
                float2 zf = __half22float2(*reinterpret_cast<__half2*>(&sz2));

                float nn0 = tanh_ap(fmaf(rf.x, Dnh[tr][i0] + bh_n[tr][0],
                                         Dnx[tr][i0] + bi_n[tr][0]));
                float nn1 = tanh_ap(fmaf(rf.y, Dnh[tr][i1] + bh_n[tr][1],
                                         Dnx[tr][i1] + bi_n[tr][1]));

                float h0 = fmaf(zf.x, hp[tr][rg][0] - nn0, nn0);
                float h1 = fmaf(zf.y, hp[tr][rg][1] - nn1, nn1);
                hp[tr][rg][0] = h0;  hp[tr][rg][1] = h1;
                hsum[tr][rg][0] += h0;  hsum[tr][rg][1] += h1;

                *reinterpret_cast<uint32_t*>(&h_sh[cur ^ 1][g + rg * 8][col]) =
                    pack_h2(h0, h1);
            }
        }

        // stage x[t+1] into the next buffer
        if (xdo)
            *reinterpret_cast<uint32_t*>(&h_sh[cur ^ 1][xb][HH + 2 * xj]) = xw;

        __syncthreads();
        cur ^= 1;
    }

#pragma unroll
    for (int tr = 0; tr < 2; tr++) {
        const int col = (2 * w + tr) * 8 + 2 * tig;
#pragma unroll
        for (int rg = 0; rg < 2; rg++) {
            out[(bg0 + g + rg * 8) * HH + col]     = hsum[tr][rg][0] * (1.0f / (float)TT);
            out[(bg0 + g + rg * 8) * HH + col + 1] = hsum[tr][rg][1] * (1.0f / (float)TT);
        }
    }
}

extern "C" void kernel_launch(void* const* d_in, const int* in_sizes, int n_in,
                              void* d_out, int out_size) {
    const float* x   = (const float*)d_in[0];
    const float* Wih = (const float*)d_in[1];
    const float* Whh = (const float*)d_in[2];
    const float* bih = (const float*)d_in[3];
    const float* bhh = (const float*)d_in[4];
    float* out = (float*)d_out;
    (void)in_sizes; (void)n_in; (void)out_size;

    gru_fused<<<NCTA, 256>>>(x, Wih, Whh, bih, bhh, out);
}

// round 17
// speedup vs baseline: 2.1618x; 1.2635x over previous
#include <cuda_runtime.h>
#include <cuda_fp16.h>
#include <cstdint>

#define BB 256
#define TT 2000
#define II 23
#define HH 128
#define MB 16                   // batches per CTA (full m16 A rows)
#define NCTA (BB / MB)          // 16
#define NSL 10                  // k-slices of 16 (128 h + 32 x/bias pad)
#define HSTRIDE 168             // padded fp16 row stride (336B; conflict-free)

__device__ __forceinline__ float tanh_ap(float x) {
    float y;
    asm("tanh.approx.f32 %0, %1;" : "=f"(y) : "f"(x));
    return y;
}
__device__ __forceinline__ uint32_t pack_h2(float lo, float hi) {
    uint32_t d;
    asm("cvt.rn.f16x2.f32 %0, %1, %2;" : "=r"(d) : "f"(hi), "f"(lo));
    return d;
}
__device__ __forceinline__ uint32_t tanh_h2(uint32_t v) {
    uint32_t d;
    asm("tanh.approx.f16x2 %0, %1;" : "=r"(d) : "r"(v));
    return d;
}
__device__ __forceinline__ uint32_t hfma2_(uint32_t a, uint32_t b, uint32_t c) {
    uint32_t d;
    asm("fma.rn.f16x2 %0, %1, %2, %3;" : "=r"(d) : "r"(a), "r"(b), "r"(c));
    return d;
}
__device__ __forceinline__ void ldsm_x4(uint32_t& r0, uint32_t& r1, uint32_t& r2,
                                        uint32_t& r3, uint32_t addr) {
    asm volatile("ldmatrix.sync.aligned.m8n8.x4.shared.b16 {%0,%1,%2,%3}, [%4];"
                 : "=r"(r0), "=r"(r1), "=r"(r2), "=r"(r3) : "r"(addr));
}
__device__ __forceinline__ void mma_f16(float& d0, float& d1, float& d2, float& d3,
                                        uint32_t a0, uint32_t a1, uint32_t a2, uint32_t a3,
                                        uint32_t b0, uint32_t b1,
                                        float c0, float c1, float c2, float c3) {
    asm volatile(
        "mma.sync.aligned.m16n8k16.row.col.f32.f16.f16.f32 "
        "{%0,%1,%2,%3},{%4,%5,%6,%7},{%8,%9},{%10,%11,%12,%13};"
        : "=f"(d0), "=f"(d1), "=f"(d2), "=f"(d3)
        : "r"(a0), "r"(a1), "r"(a2), "r"(a3), "r"(b0), "r"(b1),
          "f"(c0), "f"(c1), "f"(c2), "f"(c3));
}

// ============================================================
// Fused GRU, full-M, register-budgeted:
// grid 16, block 256 (8 warps), 16 batches/CTA.
// gates = [W_hh | W_ih | bias] . [h ; x(t) ; 1]  (K=160)
//   r,z: weights+bias pre-scaled 0.5 (sigmoid via tanh.f16x2)
//   n:   bih folded into bias column; bhh_n in regs (scaled by r)
// A fragments loaded in TWO k-halves (5 slices live at a time).
// x staged by warps 0..2 only (2 batches per staging thread).
// ============================================================
__global__ __launch_bounds__(256, 1) void gru_fused(
    const float* __restrict__ x,     // [B, T, I]
    const float* __restrict__ Wih,   // [3H, I]
    const float* __restrict__ Whh,   // [3H, H]
    const float* __restrict__ bih,   // [3H]
    const float* __restrict__ bhh,   // [3H]
    float* __restrict__ out)         // [B, H]
{
    const int tid  = threadIdx.x;
    const int w    = tid >> 5;
    const int lane = tid & 31;
    const int g    = lane >> 2;
    const int tig  = lane & 3;
    const int bg0  = blockIdx.x * MB;

    __shared__ __align__(16) __half h_sh[2][MB][HSTRIDE];

    // ---- B fragments: slices 0..7 W_hh, 8..9 W_ih + bias column (k=151) ----
    uint32_t Bf[2][3][NSL][2];
#pragma unroll
    for (int tr = 0; tr < 2; tr++) {
        const int cg = 2 * w + tr;
#pragma unroll
        for (int gate = 0; gate < 3; gate++) {
            const float sc = (gate < 2) ? 0.5f : 1.0f;
            const int orow = gate * HH + cg * 8 + g;
            const float bfold = (gate < 2) ? 0.5f * (bih[orow] + bhh[orow])
                                           : bih[orow];
            const float* WrH = Whh + (size_t)orow * HH;
#pragma unroll
            for (int ks = 0; ks < 8; ks++) {
                int c = ks * 16 + 2 * tig;
                float2 v0 = *reinterpret_cast<const float2*>(WrH + c);
                float2 v1 = *reinterpret_cast<const float2*>(WrH + c + 8);
                Bf[tr][gate][ks][0] = pack_h2(v0.x * sc, v0.y * sc);
                Bf[tr][gate][ks][1] = pack_h2(v1.x * sc, v1.y * sc);
            }
            const float* WrI = Wih + (size_t)orow * II;
#pragma unroll
            for (int s = 0; s < 2; s++) {
                int c = s * 16 + 2 * tig;
                float e0 = (c < II) ? WrI[c] * sc : 0.f;
                float e1 = (c + 1 == II) ? bfold
                         : ((c + 1 < II) ? WrI[c + 1] * sc : 0.f);
                float e2 = (c + 8 < II) ? WrI[c + 8] * sc : 0.f;
                float e3 = (c + 9 < II) ? WrI[c + 9] * sc : 0.f;
                Bf[tr][gate][8 + s][0] = pack_h2(e0, e1);
                Bf[tr][gate][8 + s][1] = pack_h2(e2, e3);
            }
        }
    }

    // b_hh for candidate gate (multiplied by r -> cannot fold)
    float bh_n[2][2];
#pragma unroll
    for (int tr = 0; tr < 2; tr++) {
        const int col = (2 * w + tr) * 8 + 2 * tig;
        bh_n[tr][0] = bhh[2 * HH + col];
        bh_n[tr][1] = bhh[2 * HH + col + 1];
    }

    // zero both buffers
    for (int i = tid; i < 2 * MB * HSTRIDE; i += 256)
        reinterpret_cast<__half*>(h_sh)[i] = __float2half(0.0f);

    // x staging (warps 0..2): thread handles word xj of batches {2bp, 2bp+1}
    const int bp = tid / 12;          // 0..7 for tid<96
    const int xj = tid % 12;
    const bool xrole = (tid < 96);
    const float* xr0 = x + (size_t)(bg0 + (xrole ? 2 * bp : 0)) * TT * II;
    const float* xr1 = xr0 + (size_t)TT * II;

    __syncthreads();

    // stage x[t=0] (scalar loads; rows only 4B-aligned); k=151 word gets 1.0
    if (xrole) {
        float a0 = xr0[2 * xj];
        float a1 = (xj < 11) ? xr0[2 * xj + 1] : 1.0f;
        float b0 = xr1[2 * xj];
        float b1 = (xj < 11) ? xr1[2 * xj + 1] : 1.0f;
        *reinterpret_cast<uint32_t*>(&h_sh[0][2 * bp][HH + 2 * xj])     = pack_h2(a0, a1);
        *reinterpret_cast<uint32_t*>(&h_sh[0][2 * bp + 1][HH + 2 * xj]) = pack_h2(b0, b1);
    }

    // per-thread h state: [tr][rowgroup][col 0/1]
    float hp[2][2][2]   = {{{0.f,0.f},{0.f,0.f}},{{0.f,0.f},{0.f,0.f}}};
    float hsum[2][2][2] = {{{0.f,0.f},{0.f,0.f}},{{0.f,0.f},{0.f,0.f}}};

    const uint32_t hoff = (lane & 15) * (HSTRIDE * 2) + (lane >> 4) * 16;
    uint32_t hbase[2];
    hbase[0] = (uint32_t)__cvta_generic_to_shared(&h_sh[0][0][0]) + hoff;
    hbase[1] = (uint32_t)__cvta_generic_to_shared(&h_sh[1][0][0]) + hoff;

    const uint32_t H05 = 0x38003800u;   // half2(0.5, 0.5)

    __syncthreads();

    int cur = 0;
    for (int t = 0; t < TT; t++) {
        // prefetch x[t+1] (threads 0..95; 4 scalar LDGs)
        uint32_t xw0 = 0u, xw1 = 0u;
        const bool xdo = xrole && (t + 1 < TT);
        if (xdo) {
            const float* p0 = xr0 + (size_t)(t + 1) * II;
            const float* p1 = xr1 + (size_t)(t + 1) * II;
            float a0 = p0[2 * xj];
            float a1 = (xj < 11) ? p0[2 * xj + 1] : 1.0f;
            float b0 = p1[2 * xj];
            float b1 = (xj < 11) ? p1[2 * xj + 1] : 1.0f;
            xw0 = pack_h2(a0, a1);
            xw1 = pack_h2(b0, b1);
        }

        // accumulators (live across both k-halves)
        float Dr[2][4]  = {{0.f,0.f,0.f,0.f},{0.f,0.f,0.f,0.f}};
        float Dz[2][4]  = {{0.f,0.f,0.f,0.f},{0.f,0.f,0.f,0.f}};
        float Dnh[2][4] = {{0.f,0.f,0.f,0.f},{0.f,0.f,0.f,0.f}};
        float Dnx[2][4] = {{0.f,0.f,0.f,0.f},{0.f,0.f,0.f,0.f}};

        // ---- two k-halves: only 5 A-slices live at a time ----
#pragma unroll
        for (int kh = 0; kh < 2; kh++) {
            uint32_t A0[5], A1[5], A2[5], A3[5];
#pragma unroll
            for (int j = 0; j < 5; j++)
                ldsm_x4(A0[j], A1[j], A2[j], A3[j],
                        hbase[cur] + (kh * 5 + j) * 32);

#pragma unroll
            for (int tr = 0; tr < 2; tr++) {
#pragma unroll
                for (int j = 0; j < 5; j++) {
                    const int ks = kh * 5 + j;
                    mma_f16(Dr[tr][0], Dr[tr][1], Dr[tr][2], Dr[tr][3],
                            A0[j], A1[j], A2[j], A3[j],
                            Bf[tr][0][ks][0], Bf[tr][0][ks][1],
                            Dr[tr][0], Dr[tr][1], Dr[tr][2], Dr[tr][3]);
                    mma_f16(Dz[tr][0], Dz[tr][1], Dz[tr][2], Dz[tr][3],
                            A0[j], A1[j], A2[j], A3[j],
                            Bf[tr][1][ks][0], Bf[tr][1][ks][1],
                            Dz[tr][0], Dz[tr][1], Dz[tr][2], Dz[tr][3]);
                    if (ks < 8)
                        mma_f16(Dnh[tr][0], Dnh[tr][1], Dnh[tr][2], Dnh[tr][3],
                                A0[j], A1[j], A2[j], A3[j],
                                Bf[tr][2][ks][0], Bf[tr][2][ks][1],
                                Dnh[tr][0], Dnh[tr][1], Dnh[tr][2], Dnh[tr][3]);
                    else
                        mma_f16(Dnx[tr][0], Dnx[tr][1], Dnx[tr][2], Dnx[tr][3],
                                A0[j], A1[j], A2[j], A3[j],
                                Bf[tr][2][ks][0], Bf[tr][2][ks][1],
                                Dnx[tr][0], Dnx[tr][1], Dnx[tr][2], Dnx[tr][3]);
                }
            }
        }

        // ---- epilogue: r,z packed tanh (biases in column); n + h fp32 ----
#pragma unroll
        for (int tr = 0; tr < 2; tr++) {
            const int col = (2 * w + tr) * 8 + 2 * tig;
#pragma unroll
            for (int rg = 0; rg < 2; rg++) {
                const int i0 = 2 * rg, i1 = 2 * rg + 1;
                uint32_t sr2 = hfma2_(tanh_h2(pack_h2(Dr[tr][i0], Dr[tr][i1])),
                                      H05, H05);
                uint32_t sz2 = hfma2_(tanh_h2(pack_h2(Dz[tr][i0], Dz[tr][i1])),
                                      H05, H05);
                float2 rf = __half22float2(*reinterpret_cast<__half2*>(&sr2));
                float2 zf = __half22float2(*reinterpret_cast<__half2*>(&sz2));

                float nn0 = tanh_ap(fmaf(rf.x, Dnh[tr][i0] + bh_n[tr][0],
                                         Dnx[tr][i0]));
                float nn1 = tanh_ap(fmaf(rf.y, Dnh[tr][i1] + bh_n[tr][1],
                                         Dnx[tr][i1]));

                float h0 = fmaf(zf.x, hp[tr][rg][0] - nn0, nn0);
                float h1 = fmaf(zf.y, hp[tr][rg][1] - nn1, nn1);
                hp[tr][rg][0] = h0;  hp[tr][rg][1] = h1;
                hsum[tr][rg][0] += h0;  hsum[tr][rg][1] += h1;

                *reinterpret_cast<uint32_t*>(&h_sh[cur ^ 1][g + rg * 8][col]) =
                    pack_h2(h0, h1);
            }
        }

        // stage x[t+1] into the next buffer
        if (xdo) {
            *reinterpret_cast<uint32_t*>(&h_sh[cur ^ 1][2 * bp][HH + 2 * xj])     = xw0;
            *reinterpret_cast<uint32_t*>(&h_sh[cur ^ 1][2 * bp + 1][HH + 2 * xj]) = xw1;
        }

        __syncthreads();
        cur ^= 1;
    }

#pragma unroll
    for (int tr = 0; tr < 2; tr++) {
        const int col = (2 * w + tr) * 8 + 2 * tig;
#pragma unroll
        for (int rg = 0; rg < 2; rg++) {
            out[(bg0 + g + rg * 8) * HH + col]     = hsum[tr][rg][0] * (1.0f / (float)TT);
            out[(bg0 + g + rg * 8) * HH + col + 1] = hsum[tr][rg][1] * (1.0f / (float)TT);
        }
    }
}

extern "C" void kernel_launch(void* const* d_in, const int* in_sizes, int n_in,
                              void* d_out, int out_size) {
    const float* x   = (const float*)d_in[0];
    const float* Wih = (const float*)d_in[1];
    const float* Whh = (const float*)d_in[2];
    const float* bih = (const float*)d_in[3];
    const float* bhh = (const float*)d_in[4];
    float* out = (float*)d_out;
    (void)in_sizes; (void)n_in; (void)out_size;

    gru_fused<<<NCTA, 256>>>(x, Wih, Whh, bih, bhh, out);
}